// round 6
// baseline (speedup 1.0000x reference)
#include <cuda_runtime.h>
#include <cuda_fp16.h>
#include <cstdint>

#define S_DIM 128
#define I_DIM 256
#define CM    256
#define CC    32
#define CZ    128
#define M1    8192   // I_DIM * CC
#define NROWS 32768  // S_DIM * I_DIM

// Scratch (device globals: allocation-free per harness rules)
__device__ __half g_Ah[(size_t)M1 * S_DIM];     // [(i,c)][s]  A/128, fp16
__device__ __half g_Bh[(size_t)M1 * S_DIM];     // [(j,d)][s]  B,     fp16
__device__ __half g_woT[CZ * 1024];             // [z][(c,d)] fp16 transposed w_out
__device__ float  g_mu[NROWS];
__device__ float  g_rs[NROWS];

// ---------------------------------------------------------------------------
// helpers
// ---------------------------------------------------------------------------
__device__ __forceinline__ unsigned f2tf32(float f) {
    unsigned r;
    asm("cvt.rna.tf32.f32 %0, %1;" : "=r"(r) : "f"(f));
    return r;
}

__device__ __forceinline__ void cp16(void* s, const void* g) {
    unsigned sa = (unsigned)__cvta_generic_to_shared(s);
    asm volatile("cp.async.cg.shared.global [%0], [%1], 16;\n" :: "r"(sa), "l"(g));
}
__device__ __forceinline__ void cp_commit() { asm volatile("cp.async.commit_group;\n"); }
template<int N> __device__ __forceinline__ void cp_wait() {
    asm volatile("cp.async.wait_group %0;\n" :: "n"(N));
}

__device__ __forceinline__ void mma_tf32(float c[4],
                                         unsigned a0, unsigned a1, unsigned a2, unsigned a3,
                                         unsigned b0, unsigned b1) {
    asm volatile(
        "mma.sync.aligned.m16n8k8.row.col.f32.tf32.tf32.f32 "
        "{%0,%1,%2,%3}, {%4,%5,%6,%7}, {%8,%9}, {%0,%1,%2,%3};"
        : "+f"(c[0]), "+f"(c[1]), "+f"(c[2]), "+f"(c[3])
        : "r"(a0), "r"(a1), "r"(a2), "r"(a3), "r"(b0), "r"(b1));
}

__device__ __forceinline__ void mma_f16(float c[4],
                                        unsigned a0, unsigned a1, unsigned a2, unsigned a3,
                                        unsigned b0, unsigned b1) {
    asm volatile(
        "mma.sync.aligned.m16n8k16.row.col.f32.f16.f16.f32 "
        "{%0,%1,%2,%3}, {%4,%5,%6,%7}, {%8,%9}, {%0,%1,%2,%3};"
        : "+f"(c[0]), "+f"(c[1]), "+f"(c[2]), "+f"(c[3])
        : "r"(a0), "r"(a1), "r"(a2), "r"(a3), "r"(b0), "r"(b1));
}

// ---------------------------------------------------------------------------
// Kernel 0: LN statistics. One warp per row (256 floats).
// ---------------------------------------------------------------------------
__global__ __launch_bounds__(256) void k_stats(const float* __restrict__ x)
{
    const int tid  = threadIdx.x;
    const int row  = blockIdx.x * 8 + (tid >> 5);
    const int lane = tid & 31;
    const float4* p = (const float4*)(x + (size_t)row * CM);
    float4 u = p[lane], v = p[lane + 32];
    float s1 = u.x + u.y + u.z + u.w + v.x + v.y + v.z + v.w;
    float s2 = u.x*u.x + u.y*u.y + u.z*u.z + u.w*u.w
             + v.x*v.x + v.y*v.y + v.z*v.z + v.w*v.w;
    #pragma unroll
    for (int o = 16; o; o >>= 1) {
        s1 += __shfl_xor_sync(0xffffffffu, s1, o);
        s2 += __shfl_xor_sync(0xffffffffu, s2, o);
    }
    if (lane == 0) {
        float mu  = s1 * (1.f / 256.f);
        float var = s2 * (1.f / 256.f) - mu * mu;
        g_mu[row] = mu;
        g_rs[row] = rsqrtf(var + 1e-5f);
    }
}

// ---------------------------------------------------------------------------
// Kernel 0b: transpose w_out -> g_woT[z][(c,d)] fp16
// ---------------------------------------------------------------------------
__global__ __launch_bounds__(256) void k_woT(const float* __restrict__ wo)
{
    const int z = blockIdx.x;
    for (int k = threadIdx.x; k < 1024; k += 256)
        g_woT[z * 1024 + k] = __float2half(wo[k * CZ + z]);
}

// ---------------------------------------------------------------------------
// Kernel 1: LN + dual projection via tensor cores (tf32 3-pass, fp32-grade).
// ---------------------------------------------------------------------------
__global__ __launch_bounds__(128) void k_proj(
    const float* __restrict__ x, const float* __restrict__ lnw, const float* __restrict__ lnb,
    const float* __restrict__ wl, const float* __restrict__ bl,
    const float* __restrict__ wr, const float* __restrict__ br)
{
    extern __shared__ float sm[];
    float* Wsm  = sm;                       // [256][72]
    float* xs   = Wsm + 256 * 72;           // 2 x [64][36]
    float* lnws = xs + 2 * 64 * 36;         // 256
    float* lnbs = lnws + 256;               // 256

    const int tid  = threadIdx.x;
    const int warp = tid >> 5, lane = tid & 31;
    const int g = lane >> 2, q = lane & 3;
    const int wm = (warp >> 1) * 32, wn = (warp & 1) * 32;
    const int m0 = blockIdx.x * 64;
    const int i  = m0 >> 7;
    const int s0 = m0 & 127;

    const float4* wl4 = (const float4*)wl;
    const float4* wr4 = (const float4*)wr;
    for (int v = tid; v < 2048; v += 128) {
        int k = v >> 3, c = (v & 7) << 2;
        *(float4*)&Wsm[k * 72 + c]      = wl4[v];
        *(float4*)&Wsm[k * 72 + 32 + c] = wr4[v];
    }
    for (int v = tid; v < 256; v += 128) { lnws[v] = lnw[v]; lnbs[v] = lnb[v]; }

    float mus[2][2], rss[2][2];
    #pragma unroll
    for (int mt = 0; mt < 2; mt++) {
        int s = s0 + wm + mt * 16 + g;
        mus[mt][0] = g_mu[s * 256 + i];       rss[mt][0] = g_rs[s * 256 + i];
        mus[mt][1] = g_mu[(s + 8) * 256 + i]; rss[mt][1] = g_rs[(s + 8) * 256 + i];
    }

    float acc[2][4][4];
    #pragma unroll
    for (int nt = 0; nt < 4; nt++) {
        int c = wn + nt * 8 + q * 2;
        float b0 = (c < 32) ? bl[c] : br[c - 32];
        float b1 = (c + 1 < 32) ? bl[c + 1] : br[c + 1 - 32];
        #pragma unroll
        for (int mt = 0; mt < 2; mt++) {
            acc[mt][nt][0] = b0; acc[mt][nt][1] = b1;
            acc[mt][nt][2] = b0; acc[mt][nt][3] = b1;
        }
    }

    auto issue = [&](int kc, int buf) {
        #pragma unroll
        for (int it = 0; it < 4; it++) {
            int v = tid + it * 128;
            int r = v >> 3, k4 = (v & 7) << 2;
            cp16(&xs[buf * 2304 + r * 36 + k4],
                 &x[(size_t)((s0 + r) * 256 + i) * CM + kc * 32 + k4]);
        }
        cp_commit();
    };

    issue(0, 0);
    int buf = 0;
    for (int kc = 0; kc < 8; kc++) {
        if (kc < 7) { issue(kc + 1, buf ^ 1); cp_wait<1>(); }
        else        { cp_wait<0>(); }
        __syncthreads();
        const float* X = &xs[buf * 2304];
        #pragma unroll
        for (int ks = 0; ks < 4; ks++) {
            int kl0 = ks * 8 + q, kl1 = kl0 + 4;
            int kg0 = kc * 32 + kl0, kg1 = kc * 32 + kl1;
            float w0 = lnws[kg0], c0 = lnbs[kg0];
            float w1 = lnws[kg1], c1 = lnbs[kg1];

            unsigned ah[2][4], al[2][4];
            #pragma unroll
            for (int mt = 0; mt < 2; mt++) {
                int mb = wm + mt * 16 + g;
                float v00 = (X[mb * 36 + kl0]       - mus[mt][0]) * rss[mt][0] * w0 + c0;
                float v10 = (X[(mb + 8) * 36 + kl0] - mus[mt][1]) * rss[mt][1] * w0 + c0;
                float v01 = (X[mb * 36 + kl1]       - mus[mt][0]) * rss[mt][0] * w1 + c1;
                float v11 = (X[(mb + 8) * 36 + kl1] - mus[mt][1]) * rss[mt][1] * w1 + c1;
                ah[mt][0] = f2tf32(v00); al[mt][0] = f2tf32(v00 - __uint_as_float(ah[mt][0]));
                ah[mt][1] = f2tf32(v10); al[mt][1] = f2tf32(v10 - __uint_as_float(ah[mt][1]));
                ah[mt][2] = f2tf32(v01); al[mt][2] = f2tf32(v01 - __uint_as_float(ah[mt][2]));
                ah[mt][3] = f2tf32(v11); al[mt][3] = f2tf32(v11 - __uint_as_float(ah[mt][3]));
            }
            unsigned bh[4][2], blo[4][2];
            #pragma unroll
            for (int nt = 0; nt < 4; nt++) {
                int n = wn + nt * 8 + g;
                float r0 = Wsm[kg0 * 72 + n], r1 = Wsm[kg1 * 72 + n];
                bh[nt][0] = f2tf32(r0); blo[nt][0] = f2tf32(r0 - __uint_as_float(bh[nt][0]));
                bh[nt][1] = f2tf32(r1); blo[nt][1] = f2tf32(r1 - __uint_as_float(bh[nt][1]));
            }
            #pragma unroll
            for (int mt = 0; mt < 2; mt++)
                #pragma unroll
                for (int nt = 0; nt < 4; nt++) {
                    mma_tf32(acc[mt][nt], ah[mt][0], ah[mt][1], ah[mt][2], ah[mt][3],
                             bh[nt][0], bh[nt][1]);
                    mma_tf32(acc[mt][nt], al[mt][0], al[mt][1], al[mt][2], al[mt][3],
                             bh[nt][0], bh[nt][1]);
                    mma_tf32(acc[mt][nt], ah[mt][0], ah[mt][1], ah[mt][2], ah[mt][3],
                             blo[nt][0], blo[nt][1]);
                }
        }
        __syncthreads();
        buf ^= 1;
    }

    // epilogue: transpose via smem, write fp16 [m][s]
    __half* T = (__half*)xs;                 // [64 cols][72 s] half
    #pragma unroll
    for (int mt = 0; mt < 2; mt++) {
        #pragma unroll
        for (int rr = 0; rr < 2; rr++) {
            int lr = wm + mt * 16 + g + rr * 8;
            #pragma unroll
            for (int nt = 0; nt < 4; nt++) {
                int col = wn + nt * 8 + q * 2;
                float v0 = acc[mt][nt][rr * 2], v1 = acc[mt][nt][rr * 2 + 1];
                if (col < 32) { v0 *= (1.f / 128.f); v1 *= (1.f / 128.f); }
                T[col * 72 + lr]       = __float2half(v0);
                T[(col + 1) * 72 + lr] = __float2half(v1);
            }
        }
    }
    __syncthreads();
    {
        int col = tid >> 1, sh = (tid & 1) * 32;
        const int4* src = (const int4*)&T[col * 72 + sh];
        __half* dst = (col < 32)
            ? &g_Ah[(size_t)(i * 32 + col) * S_DIM + s0 + sh]
            : &g_Bh[(size_t)(i * 32 + (col - 32)) * S_DIM + s0 + sh];
        int4* d4 = (int4*)dst;
        d4[0] = src[0]; d4[1] = src[1]; d4[2] = src[2]; d4[3] = src[3];
    }
}

// ---------------------------------------------------------------------------
// Kernel 2 (FUSED, 2 CTAs/SM): per CTA:
//   stage 1: S[256 x 128] computed as TWO 128x128 sub-GEMMs (64-reg acc reuse)
//            rows = 8 i x 32 c, cols = 4 j x 32 d; K = s = 128, fp16 -> smem
//   stage 2: out[32 pairs x 128 z] = S_flat[pair][1024] @ woT^T + bo
//   S smem (halves): addr = row*136 + (row>>5)*8 + col (skew: stage-2 A loads
//   conflict-free). smem total 110720 B; regs capped 128 -> occupancy 2.
// ---------------------------------------------------------------------------
#define S_ADDR(row, col) ((row) * 136 + ((row) >> 5) * 8 + (col))

__global__ __launch_bounds__(256, 2) void k_fused(const float* __restrict__ bo,
                                                  float* __restrict__ out)
{
    extern __shared__ __half sh[];
    __half* As = sh;                 // 2 x [128][40]  (5120 halves each)
    __half* Bs = sh + 10240;         // 2 x [128][40]
    __half* Bz = sh;                 // stage2 wo chunks: 2 x [128][72] (overlay)
    __half* S  = sh + 20480;         // 34880 halves

    const int tid  = threadIdx.x;
    const int warp = tid >> 5, lane = tid & 31;
    const int g = lane >> 2, q = lane & 3;
    const int m0g = blockIdx.y * 256;   // g_Ah row base (8 i x 32 c)
    const int n0g = blockIdx.x * 128;   // g_Bh row base (4 j x 32 d)

    // ------------------ stage 1: two 128x128 sub-tiles ------------------
    const int wm1 = (warp >> 2) * 64, wn1 = (warp & 3) * 32;

    for (int half = 0; half < 2; half++) {
        float acc[4][4][4];
        #pragma unroll
        for (int a = 0; a < 4; a++)
            #pragma unroll
            for (int b = 0; b < 4; b++)
                #pragma unroll
                for (int c = 0; c < 4; c++) acc[a][b][c] = 0.f;

        auto issue1 = [&](int kc, int st) {
            #pragma unroll
            for (int it = 0; it < 2; it++) {
                int v = tid + it * 256;                 // 0..511
                int r = v >> 2, ko = (v & 3) << 3;      // row, k offset (halves)
                cp16(&As[st * 5120 + r * 40 + ko],
                     &g_Ah[(size_t)(m0g + half * 128 + r) * S_DIM + kc * 32 + ko]);
                cp16(&Bs[st * 5120 + r * 40 + ko],
                     &g_Bh[(size_t)(n0g + r) * S_DIM + kc * 32 + ko]);
            }
            cp_commit();
        };

        issue1(0, 0); issue1(1, 1);
        for (int kc = 0; kc < 4; kc++) {
            if (kc < 3) cp_wait<1>(); else cp_wait<0>();
            __syncthreads();
            const __half* A = &As[(kc & 1) * 5120];
            const __half* B = &Bs[(kc & 1) * 5120];
            #pragma unroll
            for (int kw = 0; kw < 2; kw++) {
                unsigned af[4][4], bf[4][2];
                #pragma unroll
                for (int mt = 0; mt < 4; mt++) {
                    int m = wm1 + mt * 16 + g;
                    af[mt][0] = *(const unsigned*)&A[m * 40 + kw * 16 + q * 2];
                    af[mt][1] = *(const unsigned*)&A[(m + 8) * 40 + kw * 16 + q * 2];
                    af[mt][2] = *(const unsigned*)&A[m * 40 + kw * 16 + q * 2 + 8];
                    af[mt][3] = *(const unsigned*)&A[(m + 8) * 40 + kw * 16 + q * 2 + 8];
                }
                #pragma unroll
                for (int nt = 0; nt < 4; nt++) {
                    int n = wn1 + nt * 8 + g;
                    bf[nt][0] = *(const unsigned*)&B[n * 40 + kw * 16 + q * 2];
                    bf[nt][1] = *(const unsigned*)&B[n * 40 + kw * 16 + q * 2 + 8];
                }
                #pragma unroll
                for (int mt = 0; mt < 4; mt++)
                    #pragma unroll
                    for (int nt = 0; nt < 4; nt++)
                        mma_f16(acc[mt][nt], af[mt][0], af[mt][1], af[mt][2], af[mt][3],
                                bf[nt][0], bf[nt][1]);
            }
            __syncthreads();
            if (kc + 2 < 4) issue1(kc + 2, kc & 1);
        }

        // write S sub-tile (fp16, skewed)
        #pragma unroll
        for (int mt = 0; mt < 4; mt++) {
            int r0 = half * 128 + wm1 + mt * 16 + g;
            #pragma unroll
            for (int nt = 0; nt < 4; nt++) {
                int col = wn1 + nt * 8 + q * 2;
                __half2 h0, h1;
                h0.x = __float2half(acc[mt][nt][0]); h0.y = __float2half(acc[mt][nt][1]);
                h1.x = __float2half(acc[mt][nt][2]); h1.y = __float2half(acc[mt][nt][3]);
                *(__half2*)&S[S_ADDR(r0, col)]     = h0;
                *(__half2*)&S[S_ADDR(r0 + 8, col)] = h1;
            }
        }
        __syncthreads();
    }

    // ------------------ stage 2 ------------------
    // M = 32 pairs (p = j*8 + i), N = 128 z, K = 1024 (k = c*32 + d)
    const int wm2 = (warp >> 2) * 16, wn2 = (warp & 3) * 32;

    float acc2[4][4];
    #pragma unroll
    for (int b = 0; b < 4; b++)
        #pragma unroll
        for (int c = 0; c < 4; c++) acc2[b][c] = 0.f;

    auto issue2 = [&](int kc, int st) {
        #pragma unroll
        for (int it = 0; it < 4; it++) {
            int v = tid + it * 256;                 // 0..1023
            int z = v >> 3, ko = (v & 7) << 3;
            cp16(&Bz[st * 9216 + z * 72 + ko], &g_woT[z * 1024 + kc * 64 + ko]);
        }
        cp_commit();
    };

    issue2(0, 0); issue2(1, 1);
    for (int kc = 0; kc < 16; kc++) {
        if (kc < 15) cp_wait<1>(); else cp_wait<0>();
        __syncthreads();
        const __half* B = &Bz[(kc & 1) * 9216];
        #pragma unroll
        for (int kk = 0; kk < 4; kk++) {
            int kbase = kc * 64 + kk * 16;
            unsigned af[4], bf[4][2];
            {
                int p0 = wm2 + g;
                int iA = p0 & 7,        jA = p0 >> 3;
                int iB = (p0 + 8) & 7,  jB = (p0 + 8) >> 3;
                int k0 = kbase + q * 2, k1 = kbase + q * 2 + 8;
                int c0 = k0 >> 5, d0 = k0 & 31;
                int c1 = k1 >> 5, d1 = k1 & 31;
                af[0] = *(const unsigned*)&S[S_ADDR(iA * 32 + c0, jA * 32 + d0)];
                af[1] = *(const unsigned*)&S[S_ADDR(iB * 32 + c0, jB * 32 + d0)];
                af[2] = *(const unsigned*)&S[S_ADDR(iA * 32 + c1, jA * 32 + d1)];
                af[3] = *(const unsigned*)&S[S_ADDR(iB * 32 + c1, jB * 32 + d1)];
            }
            #pragma unroll
            for (int nt = 0; nt < 4; nt++) {
                int z = wn2 + nt * 8 + g;
                bf[nt][0] = *(const unsigned*)&B[z * 72 + kk * 16 + q * 2];
                bf[nt][1] = *(const unsigned*)&B[z * 72 + kk * 16 + q * 2 + 8];
            }
            #pragma unroll
            for (int nt = 0; nt < 4; nt++)
                mma_f16(acc2[nt], af[0], af[1], af[2], af[3], bf[nt][0], bf[nt][1]);
        }
        __syncthreads();
        if (kc + 2 < 16) issue2(kc + 2, kc & 1);
    }

    // epilogue
    #pragma unroll
    for (int rr = 0; rr < 2; rr++) {
        int p = wm2 + g + rr * 8;
        int ig = blockIdx.y * 8 + (p & 7);
        int jg = blockIdx.x * 4 + (p >> 3);
        size_t orow = (size_t)(ig * 256 + jg) * 128;
        #pragma unroll
        for (int nt = 0; nt < 4; nt++) {
            int z = wn2 + nt * 8 + q * 2;
            float b0 = __ldg(&bo[z]), b1 = __ldg(&bo[z + 1]);
            float2 v;
            v.x = acc2[nt][rr * 2] + b0;
            v.y = acc2[nt][rr * 2 + 1] + b1;
            *(float2*)&out[orow + z] = v;
        }
    }
}

// ---------------------------------------------------------------------------
extern "C" void kernel_launch(void* const* d_in, const int* in_sizes, int n_in,
                              void* d_out, int out_size)
{
    const float* x   = (const float*)d_in[0];
    const float* lnw = (const float*)d_in[1];
    const float* lnb = (const float*)d_in[2];
    const float* wl  = (const float*)d_in[3];
    const float* bl  = (const float*)d_in[4];
    const float* wr  = (const float*)d_in[5];
    const float* br  = (const float*)d_in[6];
    const float* wo  = (const float*)d_in[7];
    const float* bo  = (const float*)d_in[8];

    const int SMP = (256 * 72 + 2 * 64 * 36 + 512) * 4;        // 94720 B
    const int SMF = (20480 + 34880) * 2;                       // 110720 B

    cudaFuncSetAttribute(k_proj,  cudaFuncAttributeMaxDynamicSharedMemorySize, SMP);
    cudaFuncSetAttribute(k_fused, cudaFuncAttributeMaxDynamicSharedMemorySize, SMF);

    k_stats<<<4096, 256>>>(x);
    k_woT<<<128, 256>>>(wo);
    k_proj<<<512, 128, SMP>>>(x, lnw, lnb, wl, bl, wr, br);
    k_fused<<<dim3(64, 32), 256, SMF>>>(bo, (float*)d_out);
}

// round 7
// speedup vs baseline: 1.4363x; 1.4363x over previous
#include <cuda_runtime.h>
#include <cuda_fp16.h>
#include <cstdint>

#define S_DIM 128
#define I_DIM 256
#define CM    256
#define CC    32
#define CZ    128
#define M1    8192   // I_DIM * CC
#define NROWS 32768  // S_DIM * I_DIM

// Scratch (device globals: allocation-free per harness rules)
__device__ __half g_Ah[(size_t)M1 * S_DIM];     // [(i,c)][s]  A/128, fp16
__device__ __half g_Bh[(size_t)M1 * S_DIM];     // [(j,d)][s]  B,     fp16
__device__ __half g_S16[(size_t)M1 * M1];       // outer [(i,c)][(j,d)], fp16
__device__ __half g_woT[CZ * 1024];             // [z][(c,d)] fp16 transposed w_out
__device__ float  g_mu[NROWS];
__device__ float  g_rs[NROWS];

// ---------------------------------------------------------------------------
// helpers
// ---------------------------------------------------------------------------
__device__ __forceinline__ unsigned f2tf32(float f) {
    unsigned r;
    asm("cvt.rna.tf32.f32 %0, %1;" : "=r"(r) : "f"(f));
    return r;
}

__device__ __forceinline__ void cp16(void* s, const void* g) {
    unsigned sa = (unsigned)__cvta_generic_to_shared(s);
    asm volatile("cp.async.cg.shared.global [%0], [%1], 16;\n" :: "r"(sa), "l"(g));
}
__device__ __forceinline__ void cp_commit() { asm volatile("cp.async.commit_group;\n"); }
template<int N> __device__ __forceinline__ void cp_wait() {
    asm volatile("cp.async.wait_group %0;\n" :: "n"(N));
}

__device__ __forceinline__ void ldsm4(unsigned& r0, unsigned& r1, unsigned& r2, unsigned& r3,
                                      unsigned addr) {
    asm volatile("ldmatrix.sync.aligned.m8n8.x4.shared.b16 {%0,%1,%2,%3}, [%4];"
        : "=r"(r0), "=r"(r1), "=r"(r2), "=r"(r3) : "r"(addr));
}

__device__ __forceinline__ void mma_tf32(float c[4],
                                         unsigned a0, unsigned a1, unsigned a2, unsigned a3,
                                         unsigned b0, unsigned b1) {
    asm volatile(
        "mma.sync.aligned.m16n8k8.row.col.f32.tf32.tf32.f32 "
        "{%0,%1,%2,%3}, {%4,%5,%6,%7}, {%8,%9}, {%0,%1,%2,%3};"
        : "+f"(c[0]), "+f"(c[1]), "+f"(c[2]), "+f"(c[3])
        : "r"(a0), "r"(a1), "r"(a2), "r"(a3), "r"(b0), "r"(b1));
}

__device__ __forceinline__ void mma_f16(float c[4],
                                        unsigned a0, unsigned a1, unsigned a2, unsigned a3,
                                        unsigned b0, unsigned b1) {
    asm volatile(
        "mma.sync.aligned.m16n8k16.row.col.f32.f16.f16.f32 "
        "{%0,%1,%2,%3}, {%4,%5,%6,%7}, {%8,%9}, {%0,%1,%2,%3};"
        : "+f"(c[0]), "+f"(c[1]), "+f"(c[2]), "+f"(c[3])
        : "r"(a0), "r"(a1), "r"(a2), "r"(a3), "r"(b0), "r"(b1));
}

// ---------------------------------------------------------------------------
// Kernel 0: LN statistics. One warp per row (256 floats).
// ---------------------------------------------------------------------------
__global__ __launch_bounds__(256) void k_stats(const float* __restrict__ x)
{
    const int tid  = threadIdx.x;
    const int row  = blockIdx.x * 8 + (tid >> 5);
    const int lane = tid & 31;
    const float4* p = (const float4*)(x + (size_t)row * CM);
    float4 u = p[lane], v = p[lane + 32];
    float s1 = u.x + u.y + u.z + u.w + v.x + v.y + v.z + v.w;
    float s2 = u.x*u.x + u.y*u.y + u.z*u.z + u.w*u.w
             + v.x*v.x + v.y*v.y + v.z*v.z + v.w*v.w;
    #pragma unroll
    for (int o = 16; o; o >>= 1) {
        s1 += __shfl_xor_sync(0xffffffffu, s1, o);
        s2 += __shfl_xor_sync(0xffffffffu, s2, o);
    }
    if (lane == 0) {
        float mu  = s1 * (1.f / 256.f);
        float var = s2 * (1.f / 256.f) - mu * mu;
        g_mu[row] = mu;
        g_rs[row] = rsqrtf(var + 1e-5f);
    }
}

// ---------------------------------------------------------------------------
// Kernel 0b: transpose w_out -> g_woT[z][(c,d)] fp16
// ---------------------------------------------------------------------------
__global__ __launch_bounds__(256) void k_woT(const float* __restrict__ wo)
{
    const int z = blockIdx.x;
    for (int k = threadIdx.x; k < 1024; k += 256)
        g_woT[z * 1024 + k] = __float2half(wo[k * CZ + z]);
}

// ---------------------------------------------------------------------------
// Kernel 1: LN + dual projection via tensor cores (tf32 3-pass, fp32-grade).
// ---------------------------------------------------------------------------
__global__ __launch_bounds__(128) void k_proj(
    const float* __restrict__ x, const float* __restrict__ lnw, const float* __restrict__ lnb,
    const float* __restrict__ wl, const float* __restrict__ bl,
    const float* __restrict__ wr, const float* __restrict__ br)
{
    extern __shared__ float sm[];
    float* Wsm  = sm;                       // [256][72]
    float* xs   = Wsm + 256 * 72;           // 2 x [64][36]
    float* lnws = xs + 2 * 64 * 36;         // 256
    float* lnbs = lnws + 256;               // 256

    const int tid  = threadIdx.x;
    const int warp = tid >> 5, lane = tid & 31;
    const int g = lane >> 2, q = lane & 3;
    const int wm = (warp >> 1) * 32, wn = (warp & 1) * 32;
    const int m0 = blockIdx.x * 64;
    const int i  = m0 >> 7;
    const int s0 = m0 & 127;

    const float4* wl4 = (const float4*)wl;
    const float4* wr4 = (const float4*)wr;
    for (int v = tid; v < 2048; v += 128) {
        int k = v >> 3, c = (v & 7) << 2;
        *(float4*)&Wsm[k * 72 + c]      = wl4[v];
        *(float4*)&Wsm[k * 72 + 32 + c] = wr4[v];
    }
    for (int v = tid; v < 256; v += 128) { lnws[v] = lnw[v]; lnbs[v] = lnb[v]; }

    float mus[2][2], rss[2][2];
    #pragma unroll
    for (int mt = 0; mt < 2; mt++) {
        int s = s0 + wm + mt * 16 + g;
        mus[mt][0] = g_mu[s * 256 + i];       rss[mt][0] = g_rs[s * 256 + i];
        mus[mt][1] = g_mu[(s + 8) * 256 + i]; rss[mt][1] = g_rs[(s + 8) * 256 + i];
    }

    float acc[2][4][4];
    #pragma unroll
    for (int nt = 0; nt < 4; nt++) {
        int c = wn + nt * 8 + q * 2;
        float b0 = (c < 32) ? bl[c] : br[c - 32];
        float b1 = (c + 1 < 32) ? bl[c + 1] : br[c + 1 - 32];
        #pragma unroll
        for (int mt = 0; mt < 2; mt++) {
            acc[mt][nt][0] = b0; acc[mt][nt][1] = b1;
            acc[mt][nt][2] = b0; acc[mt][nt][3] = b1;
        }
    }

    auto issue = [&](int kc, int buf) {
        #pragma unroll
        for (int it = 0; it < 4; it++) {
            int v = tid + it * 128;
            int r = v >> 3, k4 = (v & 7) << 2;
            cp16(&xs[buf * 2304 + r * 36 + k4],
                 &x[(size_t)((s0 + r) * 256 + i) * CM + kc * 32 + k4]);
        }
        cp_commit();
    };

    issue(0, 0);
    int buf = 0;
    for (int kc = 0; kc < 8; kc++) {
        if (kc < 7) { issue(kc + 1, buf ^ 1); cp_wait<1>(); }
        else        { cp_wait<0>(); }
        __syncthreads();
        const float* X = &xs[buf * 2304];
        #pragma unroll
        for (int ks = 0; ks < 4; ks++) {
            int kl0 = ks * 8 + q, kl1 = kl0 + 4;
            int kg0 = kc * 32 + kl0, kg1 = kc * 32 + kl1;
            float w0 = lnws[kg0], c0 = lnbs[kg0];
            float w1 = lnws[kg1], c1 = lnbs[kg1];

            unsigned ah[2][4], al[2][4];
            #pragma unroll
            for (int mt = 0; mt < 2; mt++) {
                int mb = wm + mt * 16 + g;
                float v00 = (X[mb * 36 + kl0]       - mus[mt][0]) * rss[mt][0] * w0 + c0;
                float v10 = (X[(mb + 8) * 36 + kl0] - mus[mt][1]) * rss[mt][1] * w0 + c0;
                float v01 = (X[mb * 36 + kl1]       - mus[mt][0]) * rss[mt][0] * w1 + c1;
                float v11 = (X[(mb + 8) * 36 + kl1] - mus[mt][1]) * rss[mt][1] * w1 + c1;
                ah[mt][0] = f2tf32(v00); al[mt][0] = f2tf32(v00 - __uint_as_float(ah[mt][0]));
                ah[mt][1] = f2tf32(v10); al[mt][1] = f2tf32(v10 - __uint_as_float(ah[mt][1]));
                ah[mt][2] = f2tf32(v01); al[mt][2] = f2tf32(v01 - __uint_as_float(ah[mt][2]));
                ah[mt][3] = f2tf32(v11); al[mt][3] = f2tf32(v11 - __uint_as_float(ah[mt][3]));
            }
            unsigned bh[4][2], blo[4][2];
            #pragma unroll
            for (int nt = 0; nt < 4; nt++) {
                int n = wn + nt * 8 + g;
                float r0 = Wsm[kg0 * 72 + n], r1 = Wsm[kg1 * 72 + n];
                bh[nt][0] = f2tf32(r0); blo[nt][0] = f2tf32(r0 - __uint_as_float(bh[nt][0]));
                bh[nt][1] = f2tf32(r1); blo[nt][1] = f2tf32(r1 - __uint_as_float(bh[nt][1]));
            }
            #pragma unroll
            for (int mt = 0; mt < 2; mt++)
                #pragma unroll
                for (int nt = 0; nt < 4; nt++) {
                    mma_tf32(acc[mt][nt], ah[mt][0], ah[mt][1], ah[mt][2], ah[mt][3],
                             bh[nt][0], bh[nt][1]);
                    mma_tf32(acc[mt][nt], al[mt][0], al[mt][1], al[mt][2], al[mt][3],
                             bh[nt][0], bh[nt][1]);
                    mma_tf32(acc[mt][nt], ah[mt][0], ah[mt][1], ah[mt][2], ah[mt][3],
                             blo[nt][0], blo[nt][1]);
                }
        }
        __syncthreads();
        buf ^= 1;
    }

    // epilogue: transpose via smem, write fp16 [m][s]
    __half* T = (__half*)xs;                 // [64 cols][72 s] half
    #pragma unroll
    for (int mt = 0; mt < 2; mt++) {
        #pragma unroll
        for (int rr = 0; rr < 2; rr++) {
            int lr = wm + mt * 16 + g + rr * 8;
            #pragma unroll
            for (int nt = 0; nt < 4; nt++) {
                int col = wn + nt * 8 + q * 2;
                float v0 = acc[mt][nt][rr * 2], v1 = acc[mt][nt][rr * 2 + 1];
                if (col < 32) { v0 *= (1.f / 128.f); v1 *= (1.f / 128.f); }
                T[col * 72 + lr]       = __float2half(v0);
                T[(col + 1) * 72 + lr] = __float2half(v1);
            }
        }
    }
    __syncthreads();
    {
        int col = tid >> 1, sh = (tid & 1) * 32;
        const int4* src = (const int4*)&T[col * 72 + sh];
        __half* dst = (col < 32)
            ? &g_Ah[(size_t)(i * 32 + col) * S_DIM + s0 + sh]
            : &g_Bh[(size_t)(i * 32 + (col - 32)) * S_DIM + s0 + sh];
        int4* d4 = (int4*)dst;
        d4[0] = src[0]; d4[1] = src[1]; d4[2] = src[2]; d4[3] = src[3];
    }
}

// ---------------------------------------------------------------------------
// Kernel 2: outer GEMM (fp16)  S[m][n] = sum_s Ah[m][s] * Bh[n][s]
//   M = N = 8192, K = 128 fully smem-resident (A 128x136, B 128x136 halves).
//   ONE load phase, ONE barrier, then 8 k16 steps of pure LDSM+HMMA.
//   8 warps, warp tile 64x32, 2 CTAs/SM.
// ---------------------------------------------------------------------------
__global__ __launch_bounds__(256, 2) void k_outer()
{
    extern __shared__ __half smh[];
    __half* As = smh;               // [128][136]
    __half* Bs = smh + 17408;       // [128][136]

    const int tid  = threadIdx.x;
    const int warp = tid >> 5, lane = tid & 31;
    const int g = lane >> 2, q = lane & 3;
    const int wm = (warp >> 2) * 64, wn = (warp & 3) * 32;
    const int m0 = blockIdx.x * 128, n0 = blockIdx.y * 128;

    const int mat  = lane >> 3;
    const int lrow = (mat & 1) * 8 + (lane & 7);
    const int lcol = (mat >> 1) * 8;

    // load full tiles (2048 cp16 per array)
    #pragma unroll
    for (int it = 0; it < 8; it++) {
        int v = tid + it * 256;                 // 0..2047
        int r = v >> 4, ko = (v & 15) << 3;     // row, k offset (halves)
        cp16(&As[r * 136 + ko], &g_Ah[(size_t)(m0 + r) * S_DIM + ko]);
        cp16(&Bs[r * 136 + ko], &g_Bh[(size_t)(n0 + r) * S_DIM + ko]);
    }
    cp_commit();

    float acc[4][4][4];
    #pragma unroll
    for (int a = 0; a < 4; a++)
        #pragma unroll
        for (int b = 0; b < 4; b++)
            #pragma unroll
            for (int c = 0; c < 4; c++) acc[a][b][c] = 0.f;

    cp_wait<0>();
    __syncthreads();

    const unsigned Ab = (unsigned)__cvta_generic_to_shared(As);
    const unsigned Bb = (unsigned)__cvta_generic_to_shared(Bs);

    #pragma unroll
    for (int kk = 0; kk < 8; kk++) {
        unsigned af[4][4], bf[4][2];
        #pragma unroll
        for (int mt = 0; mt < 4; mt++) {
            unsigned a = Ab + (unsigned)(((wm + mt * 16 + lrow) * 136 + kk * 16 + lcol) * 2);
            ldsm4(af[mt][0], af[mt][1], af[mt][2], af[mt][3], a);
        }
        #pragma unroll
        for (int p = 0; p < 2; p++) {
            unsigned a = Bb + (unsigned)(((wn + p * 16 + lrow) * 136 + kk * 16 + lcol) * 2);
            ldsm4(bf[2*p][0], bf[2*p+1][0], bf[2*p][1], bf[2*p+1][1], a);
        }
        #pragma unroll
        for (int mt = 0; mt < 4; mt++)
            #pragma unroll
            for (int nt = 0; nt < 4; nt++)
                mma_f16(acc[mt][nt], af[mt][0], af[mt][1], af[mt][2], af[mt][3],
                        bf[nt][0], bf[nt][1]);
    }

    // epilogue: fp16 store
    #pragma unroll
    for (int mt = 0; mt < 4; mt++) {
        int r0 = m0 + wm + mt * 16 + g;
        #pragma unroll
        for (int nt = 0; nt < 4; nt++) {
            int c = n0 + wn + nt * 8 + q * 2;
            __half2 h0, h1;
            h0.x = __float2half(acc[mt][nt][0]); h0.y = __float2half(acc[mt][nt][1]);
            h1.x = __float2half(acc[mt][nt][2]); h1.y = __float2half(acc[mt][nt][3]);
            *(__half2*)&g_S16[(size_t)r0 * M1 + c]       = h0;
            *(__half2*)&g_S16[(size_t)(r0 + 8) * M1 + c] = h1;
        }
    }
}

// ---------------------------------------------------------------------------
// Kernel 3 (fp16): out[i][j][z] = sum_{c,d} S[(i,c)][(j,d)] * woT[z][(c,d)] + bo[z]
//   CTA: one i, 128 j (jb half), 128 z. K=1024 in 16 chunks of 64 halves,
//   double-buffered. 8 warps, warp tile 64x32, LDSM fragments. 2 CTAs/SM.
// ---------------------------------------------------------------------------
__global__ __launch_bounds__(256, 2) void k_proj2(const float* __restrict__ bo,
                                                  float* __restrict__ out)
{
    extern __shared__ __half smh[];
    __half* As = smh;               // 2 x [128][72]  (9216 halves each)
    __half* Bs = smh + 18432;       // 2 x [128][72]

    const int tid  = threadIdx.x;
    const int warp = tid >> 5, lane = tid & 31;
    const int g = lane >> 2, q = lane & 3;
    const int wm = (warp >> 2) * 64, wn = (warp & 3) * 32;
    const int jb = blockIdx.x, i = blockIdx.y;

    const int mat  = lane >> 3;
    const int lrow = (mat & 1) * 8 + (lane & 7);
    const int lcol = (mat >> 1) * 8;

    float acc[4][4][4];
    #pragma unroll
    for (int a = 0; a < 4; a++)
        #pragma unroll
        for (int b = 0; b < 4; b++)
            #pragma unroll
            for (int c = 0; c < 4; c++) acc[a][b][c] = 0.f;

    auto issue = [&](int kc, int st) {
        #pragma unroll
        for (int it = 0; it < 4; it++) {
            int v = tid + it * 256;                 // 0..1023
            int r = v >> 3, ks = (v & 7) << 3;      // row, k offset in chunk (halves)
            int cc = 2 * kc + (ks >> 5), d = ks & 31;
            cp16(&As[st * 9216 + r * 72 + ks],
                 &g_S16[(size_t)(i * 32 + cc) * M1 + jb * 4096 + r * 32 + d]);
            cp16(&Bs[st * 9216 + r * 72 + ks], &g_woT[r * 1024 + kc * 64 + ks]);
        }
        cp_commit();
    };

    issue(0, 0); issue(1, 1);
    for (int kc = 0; kc < 16; kc++) {
        if (kc < 15) cp_wait<1>(); else cp_wait<0>();
        __syncthreads();
        const unsigned Ab = (unsigned)__cvta_generic_to_shared(&As[(kc & 1) * 9216]);
        const unsigned Bb = (unsigned)__cvta_generic_to_shared(&Bs[(kc & 1) * 9216]);
        #pragma unroll
        for (int kk = 0; kk < 4; kk++) {
            unsigned af[4][4], bf[4][2];
            #pragma unroll
            for (int mt = 0; mt < 4; mt++) {
                unsigned a = Ab + (unsigned)(((wm + mt * 16 + lrow) * 72 + kk * 16 + lcol) * 2);
                ldsm4(af[mt][0], af[mt][1], af[mt][2], af[mt][3], a);
            }
            #pragma unroll
            for (int p = 0; p < 2; p++) {
                unsigned a = Bb + (unsigned)(((wn + p * 16 + lrow) * 72 + kk * 16 + lcol) * 2);
                ldsm4(bf[2*p][0], bf[2*p+1][0], bf[2*p][1], bf[2*p+1][1], a);
            }
            #pragma unroll
            for (int mt = 0; mt < 4; mt++)
                #pragma unroll
                for (int nt = 0; nt < 4; nt++)
                    mma_f16(acc[mt][nt], af[mt][0], af[mt][1], af[mt][2], af[mt][3],
                            bf[nt][0], bf[nt][1]);
        }
        __syncthreads();
        if (kc + 2 < 16) issue(kc + 2, kc & 1);
    }

    #pragma unroll
    for (int mt = 0; mt < 4; mt++) {
        int j = jb * 128 + wm + mt * 16 + g;
        #pragma unroll
        for (int nt = 0; nt < 4; nt++) {
            int z = wn + nt * 8 + q * 2;
            float b0 = __ldg(&bo[z]), b1 = __ldg(&bo[z + 1]);
            float2 v0, v1;
            v0.x = acc[mt][nt][0] + b0; v0.y = acc[mt][nt][1] + b1;
            v1.x = acc[mt][nt][2] + b0; v1.y = acc[mt][nt][3] + b1;
            *(float2*)&out[(size_t)(i * 256 + j) * 128 + z]     = v0;
            *(float2*)&out[(size_t)(i * 256 + j + 8) * 128 + z] = v1;
        }
    }
}

// ---------------------------------------------------------------------------
extern "C" void kernel_launch(void* const* d_in, const int* in_sizes, int n_in,
                              void* d_out, int out_size)
{
    const float* x   = (const float*)d_in[0];
    const float* lnw = (const float*)d_in[1];
    const float* lnb = (const float*)d_in[2];
    const float* wl  = (const float*)d_in[3];
    const float* bl  = (const float*)d_in[4];
    const float* wr  = (const float*)d_in[5];
    const float* br  = (const float*)d_in[6];
    const float* wo  = (const float*)d_in[7];
    const float* bo  = (const float*)d_in[8];

    const int SMP = (256 * 72 + 2 * 64 * 36 + 512) * 4;        // 94720 B
    const int SM2 = 2 * 17408 * 2;                             // 69632 B
    const int SM3 = 2 * 18432 * 2;                             // 73728 B

    cudaFuncSetAttribute(k_proj,  cudaFuncAttributeMaxDynamicSharedMemorySize, SMP);
    cudaFuncSetAttribute(k_outer, cudaFuncAttributeMaxDynamicSharedMemorySize, SM2);
    cudaFuncSetAttribute(k_proj2, cudaFuncAttributeMaxDynamicSharedMemorySize, SM3);

    k_stats<<<4096, 256>>>(x);
    k_woT<<<128, 256>>>(wo);
    k_proj<<<512, 128, SMP>>>(x, lnw, lnb, wl, bl, wr, br);
    k_outer<<<dim3(64, 64), 256, SM2>>>();
    k_proj2<<<dim3(2, 256), 256, SM3>>>(bo, (float*)d_out);
}

// round 9
// speedup vs baseline: 1.5959x; 1.1112x over previous
#include <cuda_runtime.h>
#include <cuda_fp16.h>
#include <cstdint>

#define S_DIM 128
#define I_DIM 256
#define CM    256
#define CC    32
#define CZ    128
#define M1    8192   // I_DIM * CC
#define NROWS 32768  // S_DIM * I_DIM

// Scratch (device globals: allocation-free per harness rules)
__device__ __half g_Ah[(size_t)M1 * S_DIM];     // [(i,c)][s]  A/128, fp16
__device__ __half g_Bh[(size_t)M1 * S_DIM];     // [(j,d)][s]  B,     fp16
__device__ __half g_S16[(size_t)M1 * M1];       // outer [(i,c)][(j,d)], fp16
__device__ __half g_woT[CZ * 1024];             // [z][(c,d)] fp16 transposed w_out
__device__ float  g_mu[NROWS];
__device__ float  g_rs[NROWS];

// ---------------------------------------------------------------------------
// helpers
// ---------------------------------------------------------------------------
__device__ __forceinline__ unsigned f2tf32(float f) {
    unsigned r;
    asm("cvt.rna.tf32.f32 %0, %1;" : "=r"(r) : "f"(f));
    return r;
}

__device__ __forceinline__ void cp16(void* s, const void* g) {
    unsigned sa = (unsigned)__cvta_generic_to_shared(s);
    asm volatile("cp.async.cg.shared.global [%0], [%1], 16;\n" :: "r"(sa), "l"(g));
}
__device__ __forceinline__ void cp_commit() { asm volatile("cp.async.commit_group;\n"); }
template<int N> __device__ __forceinline__ void cp_wait() {
    asm volatile("cp.async.wait_group %0;\n" :: "n"(N));
}

__device__ __forceinline__ void ldsm4(unsigned& r0, unsigned& r1, unsigned& r2, unsigned& r3,
                                      unsigned addr) {
    asm volatile("ldmatrix.sync.aligned.m8n8.x4.shared.b16 {%0,%1,%2,%3}, [%4];"
        : "=r"(r0), "=r"(r1), "=r"(r2), "=r"(r3) : "r"(addr));
}

__device__ __forceinline__ void mma_tf32(float c[4],
                                         unsigned a0, unsigned a1, unsigned a2, unsigned a3,
                                         unsigned b0, unsigned b1) {
    asm volatile(
        "mma.sync.aligned.m16n8k8.row.col.f32.tf32.tf32.f32 "
        "{%0,%1,%2,%3}, {%4,%5,%6,%7}, {%8,%9}, {%0,%1,%2,%3};"
        : "+f"(c[0]), "+f"(c[1]), "+f"(c[2]), "+f"(c[3])
        : "r"(a0), "r"(a1), "r"(a2), "r"(a3), "r"(b0), "r"(b1));
}

__device__ __forceinline__ void mma_f16(float c[4],
                                        unsigned a0, unsigned a1, unsigned a2, unsigned a3,
                                        unsigned b0, unsigned b1) {
    asm volatile(
        "mma.sync.aligned.m16n8k16.row.col.f32.f16.f16.f32 "
        "{%0,%1,%2,%3}, {%4,%5,%6,%7}, {%8,%9}, {%0,%1,%2,%3};"
        : "+f"(c[0]), "+f"(c[1]), "+f"(c[2]), "+f"(c[3])
        : "r"(a0), "r"(a1), "r"(a2), "r"(a3), "r"(b0), "r"(b1));
}

// ---------------------------------------------------------------------------
// Kernel 0: LN statistics. One warp per row (256 floats).
// ---------------------------------------------------------------------------
__global__ __launch_bounds__(256) void k_stats(const float* __restrict__ x)
{
    const int tid  = threadIdx.x;
    const int row  = blockIdx.x * 8 + (tid >> 5);
    const int lane = tid & 31;
    const float4* p = (const float4*)(x + (size_t)row * CM);
    float4 u = p[lane], v = p[lane + 32];
    float s1 = u.x + u.y + u.z + u.w + v.x + v.y + v.z + v.w;
    float s2 = u.x*u.x + u.y*u.y + u.z*u.z + u.w*u.w
             + v.x*v.x + v.y*v.y + v.z*v.z + v.w*v.w;
    #pragma unroll
    for (int o = 16; o; o >>= 1) {
        s1 += __shfl_xor_sync(0xffffffffu, s1, o);
        s2 += __shfl_xor_sync(0xffffffffu, s2, o);
    }
    if (lane == 0) {
        float mu  = s1 * (1.f / 256.f);
        float var = s2 * (1.f / 256.f) - mu * mu;
        g_mu[row] = mu;
        g_rs[row] = rsqrtf(var + 1e-5f);
    }
}

// ---------------------------------------------------------------------------
// Kernel 0b: transpose w_out -> g_woT[z][(c,d)] fp16
// ---------------------------------------------------------------------------
__global__ __launch_bounds__(256) void k_woT(const float* __restrict__ wo)
{
    const int z = blockIdx.x;
    for (int k = threadIdx.x; k < 1024; k += 256)
        g_woT[z * 1024 + k] = __float2half(wo[k * CZ + z]);
}

// ---------------------------------------------------------------------------
// Kernel 1: LN + dual projection via tensor cores (single-pass tf32).
//   (3-pass hi/lo dropped: A/B get rounded to fp16 immediately after, so the
//   extra passes were measured to contribute nothing to final rel_err.)
// ---------------------------------------------------------------------------
__global__ __launch_bounds__(128) void k_proj(
    const float* __restrict__ x, const float* __restrict__ lnw, const float* __restrict__ lnb,
    const float* __restrict__ wl, const float* __restrict__ bl,
    const float* __restrict__ wr, const float* __restrict__ br)
{
    extern __shared__ float sm[];
    float* Wsm  = sm;                       // [256][72]
    float* xs   = Wsm + 256 * 72;           // 2 x [64][36]
    float* lnws = xs + 2 * 64 * 36;         // 256
    float* lnbs = lnws + 256;               // 256

    const int tid  = threadIdx.x;
    const int warp = tid >> 5, lane = tid & 31;
    const int g = lane >> 2, q = lane & 3;
    const int wm = (warp >> 1) * 32, wn = (warp & 1) * 32;
    const int m0 = blockIdx.x * 64;
    const int i  = m0 >> 7;
    const int s0 = m0 & 127;

    const float4* wl4 = (const float4*)wl;
    const float4* wr4 = (const float4*)wr;
    for (int v = tid; v < 2048; v += 128) {
        int k = v >> 3, c = (v & 7) << 2;
        *(float4*)&Wsm[k * 72 + c]      = wl4[v];
        *(float4*)&Wsm[k * 72 + 32 + c] = wr4[v];
    }
    for (int v = tid; v < 256; v += 128) { lnws[v] = lnw[v]; lnbs[v] = lnb[v]; }

    float mus[2][2], rss[2][2];
    #pragma unroll
    for (int mt = 0; mt < 2; mt++) {
        int s = s0 + wm + mt * 16 + g;
        mus[mt][0] = g_mu[s * 256 + i];       rss[mt][0] = g_rs[s * 256 + i];
        mus[mt][1] = g_mu[(s + 8) * 256 + i]; rss[mt][1] = g_rs[(s + 8) * 256 + i];
    }

    float acc[2][4][4];
    #pragma unroll
    for (int nt = 0; nt < 4; nt++) {
        int c = wn + nt * 8 + q * 2;
        float b0 = (c < 32) ? bl[c] : br[c - 32];
        float b1 = (c + 1 < 32) ? bl[c + 1] : br[c + 1 - 32];
        #pragma unroll
        for (int mt = 0; mt < 2; mt++) {
            acc[mt][nt][0] = b0; acc[mt][nt][1] = b1;
            acc[mt][nt][2] = b0; acc[mt][nt][3] = b1;
        }
    }

    auto issue = [&](int kc, int buf) {
        #pragma unroll
        for (int it = 0; it < 4; it++) {
            int v = tid + it * 128;
            int r = v >> 3, k4 = (v & 7) << 2;
            cp16(&xs[buf * 2304 + r * 36 + k4],
                 &x[(size_t)((s0 + r) * 256 + i) * CM + kc * 32 + k4]);
        }
        cp_commit();
    };

    issue(0, 0);
    int buf = 0;
    for (int kc = 0; kc < 8; kc++) {
        if (kc < 7) { issue(kc + 1, buf ^ 1); cp_wait<1>(); }
        else        { cp_wait<0>(); }
        __syncthreads();
        const float* X = &xs[buf * 2304];
        #pragma unroll
        for (int ks = 0; ks < 4; ks++) {
            int kl0 = ks * 8 + q, kl1 = kl0 + 4;
            int kg0 = kc * 32 + kl0, kg1 = kc * 32 + kl1;
            float w0 = lnws[kg0], c0 = lnbs[kg0];
            float w1 = lnws[kg1], c1 = lnbs[kg1];

            unsigned ah[2][4];
            #pragma unroll
            for (int mt = 0; mt < 2; mt++) {
                int mb = wm + mt * 16 + g;
                float v00 = (X[mb * 36 + kl0]       - mus[mt][0]) * rss[mt][0] * w0 + c0;
                float v10 = (X[(mb + 8) * 36 + kl0] - mus[mt][1]) * rss[mt][1] * w0 + c0;
                float v01 = (X[mb * 36 + kl1]       - mus[mt][0]) * rss[mt][0] * w1 + c1;
                float v11 = (X[(mb + 8) * 36 + kl1] - mus[mt][1]) * rss[mt][1] * w1 + c1;
                ah[mt][0] = f2tf32(v00);
                ah[mt][1] = f2tf32(v10);
                ah[mt][2] = f2tf32(v01);
                ah[mt][3] = f2tf32(v11);
            }
            unsigned bh[4][2];
            #pragma unroll
            for (int nt = 0; nt < 4; nt++) {
                int n = wn + nt * 8 + g;
                bh[nt][0] = f2tf32(Wsm[kg0 * 72 + n]);
                bh[nt][1] = f2tf32(Wsm[kg1 * 72 + n]);
            }
            #pragma unroll
            for (int mt = 0; mt < 2; mt++)
                #pragma unroll
                for (int nt = 0; nt < 4; nt++)
                    mma_tf32(acc[mt][nt], ah[mt][0], ah[mt][1], ah[mt][2], ah[mt][3],
                             bh[nt][0], bh[nt][1]);
        }
        __syncthreads();
        buf ^= 1;
    }

    // epilogue: transpose via smem, write fp16 [m][s]
    __half* T = (__half*)xs;                 // [64 cols][72 s] half
    #pragma unroll
    for (int mt = 0; mt < 2; mt++) {
        #pragma unroll
        for (int rr = 0; rr < 2; rr++) {
            int lr = wm + mt * 16 + g + rr * 8;
            #pragma unroll
            for (int nt = 0; nt < 4; nt++) {
                int col = wn + nt * 8 + q * 2;
                float v0 = acc[mt][nt][rr * 2], v1 = acc[mt][nt][rr * 2 + 1];
                if (col < 32) { v0 *= (1.f / 128.f); v1 *= (1.f / 128.f); }
                T[col * 72 + lr]       = __float2half(v0);
                T[(col + 1) * 72 + lr] = __float2half(v1);
            }
        }
    }
    __syncthreads();
    {
        int col = tid >> 1, sh = (tid & 1) * 32;
        const int4* src = (const int4*)&T[col * 72 + sh];
        __half* dst = (col < 32)
            ? &g_Ah[(size_t)(i * 32 + col) * S_DIM + s0 + sh]
            : &g_Bh[(size_t)(i * 32 + (col - 32)) * S_DIM + s0 + sh];
        int4* d4 = (int4*)dst;
        d4[0] = src[0]; d4[1] = src[1]; d4[2] = src[2]; d4[3] = src[3];
    }
}

// ---------------------------------------------------------------------------
// Kernel 2: outer GEMM (fp16)  S[m][n] = sum_s Ah[m][s] * Bh[n][s]
//   M = N = 8192, K = 128 fully smem-resident (A 128x136, B 128x136 halves).
//   ONE load phase, ONE barrier, then 8 k16 steps of pure LDSM+HMMA.
//   Epilogue staged through smem (reuse A tile) for coalesced STG.128.
//   8 warps, warp tile 64x32, 2 CTAs/SM.
// ---------------------------------------------------------------------------
__global__ __launch_bounds__(256, 2) void k_outer()
{
    extern __shared__ __half smh[];
    __half* As = smh;               // [128][136]
    __half* Bs = smh + 17408;       // [128][136]

    const int tid  = threadIdx.x;
    const int warp = tid >> 5, lane = tid & 31;
    const int g = lane >> 2, q = lane & 3;
    const int wm = (warp >> 2) * 64, wn = (warp & 3) * 32;
    const int m0 = blockIdx.x * 128, n0 = blockIdx.y * 128;

    const int mat  = lane >> 3;
    const int lrow = (mat & 1) * 8 + (lane & 7);
    const int lcol = (mat >> 1) * 8;

    // load full tiles (2048 cp16 per array)
    #pragma unroll
    for (int it = 0; it < 8; it++) {
        int v = tid + it * 256;                 // 0..2047
        int r = v >> 4, ko = (v & 15) << 3;     // row, k offset (halves)
        cp16(&As[r * 136 + ko], &g_Ah[(size_t)(m0 + r) * S_DIM + ko]);
        cp16(&Bs[r * 136 + ko], &g_Bh[(size_t)(n0 + r) * S_DIM + ko]);
    }
    cp_commit();

    float acc[4][4][4];
    #pragma unroll
    for (int a = 0; a < 4; a++)
        #pragma unroll
        for (int b = 0; b < 4; b++)
            #pragma unroll
            for (int c = 0; c < 4; c++) acc[a][b][c] = 0.f;

    cp_wait<0>();
    __syncthreads();

    const unsigned Ab = (unsigned)__cvta_generic_to_shared(As);
    const unsigned Bb = (unsigned)__cvta_generic_to_shared(Bs);

    #pragma unroll
    for (int kk = 0; kk < 8; kk++) {
        unsigned af[4][4], bf[4][2];
        #pragma unroll
        for (int mt = 0; mt < 4; mt++) {
            unsigned a = Ab + (unsigned)(((wm + mt * 16 + lrow) * 136 + kk * 16 + lcol) * 2);
            ldsm4(af[mt][0], af[mt][1], af[mt][2], af[mt][3], a);
        }
        #pragma unroll
        for (int p = 0; p < 2; p++) {
            unsigned a = Bb + (unsigned)(((wn + p * 16 + lrow) * 136 + kk * 16 + lcol) * 2);
            ldsm4(bf[2*p][0], bf[2*p+1][0], bf[2*p][1], bf[2*p+1][1], a);
        }
        #pragma unroll
        for (int mt = 0; mt < 4; mt++)
            #pragma unroll
            for (int nt = 0; nt < 4; nt++)
                mma_f16(acc[mt][nt], af[mt][0], af[mt][1], af[mt][2], af[mt][3],
                        bf[nt][0], bf[nt][1]);
    }

    // epilogue: stage fp16 S tile in smem (reuse As, pitch 136 -> frag stores
    // hit banks 4g+q: conflict-free), then fully-coalesced int4 stores.
    __syncthreads();
    __half* St = As;
    #pragma unroll
    for (int mt = 0; mt < 4; mt++) {
        int r0 = wm + mt * 16 + g;
        #pragma unroll
        for (int nt = 0; nt < 4; nt++) {
            int c = wn + nt * 8 + q * 2;
            __half2 h0, h1;
            h0.x = __float2half(acc[mt][nt][0]); h0.y = __float2half(acc[mt][nt][1]);
            h1.x = __float2half(acc[mt][nt][2]); h1.y = __float2half(acc[mt][nt][3]);
            *(__half2*)&St[r0 * 136 + c]       = h0;
            *(__half2*)&St[(r0 + 8) * 136 + c] = h1;
        }
    }
    __syncthreads();
    #pragma unroll
    for (int it = 0; it < 8; it++) {
        int t = tid + it * 256;                 // 0..2047
        int r = t >> 4, seg = t & 15;           // row, 8-half segment
        int4 w = *(const int4*)&St[r * 136 + seg * 8];
        *(int4*)&g_S16[(size_t)(m0 + r) * M1 + n0 + seg * 8] = w;
    }
}

// ---------------------------------------------------------------------------
// Kernel 3 (fp16): out[i][j][z] = sum_{c,d} S[(i,c)][(j,d)] * woT[z][(c,d)] + bo[z]
//   CTA: one i, 128 j (jb half), 128 z. K=1024 in 16 chunks of 64 halves,
//   double-buffered. 8 warps, warp tile 64x32, LDSM fragments. 2 CTAs/SM.
// ---------------------------------------------------------------------------
__global__ __launch_bounds__(256, 2) void k_proj2(const float* __restrict__ bo,
                                                  float* __restrict__ out)
{
    extern __shared__ __half smh[];
    __half* As = smh;               // 2 x [128][72]  (9216 halves each)
    __half* Bs = smh + 18432;       // 2 x [128][72]

    const int tid  = threadIdx.x;
    const int warp = tid >> 5, lane = tid & 31;
    const int g = lane >> 2, q = lane & 3;
    const int wm = (warp >> 2) * 64, wn = (warp & 3) * 32;
    const int jb = blockIdx.x, i = blockIdx.y;

    const int mat  = lane >> 3;
    const int lrow = (mat & 1) * 8 + (lane & 7);
    const int lcol = (mat >> 1) * 8;

    float acc[4][4][4];
    #pragma unroll
    for (int a = 0; a < 4; a++)
        #pragma unroll
        for (int b = 0; b < 4; b++)
            #pragma unroll
            for (int c = 0; c < 4; c++) acc[a][b][c] = 0.f;

    auto issue = [&](int kc, int st) {
        #pragma unroll
        for (int it = 0; it < 4; it++) {
            int v = tid + it * 256;                 // 0..1023
            int r = v >> 3, ks = (v & 7) << 3;      // row, k offset in chunk (halves)
            int cc = 2 * kc + (ks >> 5), d = ks & 31;
            cp16(&As[st * 9216 + r * 72 + ks],
                 &g_S16[(size_t)(i * 32 + cc) * M1 + jb * 4096 + r * 32 + d]);
            cp16(&Bs[st * 9216 + r * 72 + ks], &g_woT[r * 1024 + kc * 64 + ks]);
        }
        cp_commit();
    };

    issue(0, 0); issue(1, 1);
    for (int kc = 0; kc < 16; kc++) {
        if (kc < 15) cp_wait<1>(); else cp_wait<0>();
        __syncthreads();
        const unsigned Ab = (unsigned)__cvta_generic_to_shared(&As[(kc & 1) * 9216]);
        const unsigned Bb = (unsigned)__cvta_generic_to_shared(&Bs[(kc & 1) * 9216]);
        #pragma unroll
        for (int kk = 0; kk < 4; kk++) {
            unsigned af[4][4], bf[4][2];
            #pragma unroll
            for (int mt = 0; mt < 4; mt++) {
                unsigned a = Ab + (unsigned)(((wm + mt * 16 + lrow) * 72 + kk * 16 + lcol) * 2);
                ldsm4(af[mt][0], af[mt][1], af[mt][2], af[mt][3], a);
            }
            #pragma unroll
            for (int p = 0; p < 2; p++) {
                unsigned a = Bb + (unsigned)(((wn + p * 16 + lrow) * 72 + kk * 16 + lcol) * 2);
                ldsm4(bf[2*p][0], bf[2*p+1][0], bf[2*p][1], bf[2*p+1][1], a);
            }
            #pragma unroll
            for (int mt = 0; mt < 4; mt++)
                #pragma unroll
                for (int nt = 0; nt < 4; nt++)
                    mma_f16(acc[mt][nt], af[mt][0], af[mt][1], af[mt][2], af[mt][3],
                            bf[nt][0], bf[nt][1]);
        }
        __syncthreads();
        if (kc + 2 < 16) issue(kc + 2, kc & 1);
    }

    #pragma unroll
    for (int mt = 0; mt < 4; mt++) {
        int j = jb * 128 + wm + mt * 16 + g;
        #pragma unroll
        for (int nt = 0; nt < 4; nt++) {
            int z = wn + nt * 8 + q * 2;
            float b0 = __ldg(&bo[z]), b1 = __ldg(&bo[z + 1]);
            float2 v0, v1;
            v0.x = acc[mt][nt][0] + b0; v0.y = acc[mt][nt][1] + b1;
            v1.x = acc[mt][nt][2] + b0; v1.y = acc[mt][nt][3] + b1;
            *(float2*)&out[(size_t)(i * 256 + j) * 128 + z]     = v0;
            *(float2*)&out[(size_t)(i * 256 + j + 8) * 128 + z] = v1;
        }
    }
}

// ---------------------------------------------------------------------------
extern "C" void kernel_launch(void* const* d_in, const int* in_sizes, int n_in,
                              void* d_out, int out_size)
{
    const float* x   = (const float*)d_in[0];
    const float* lnw = (const float*)d_in[1];
    const float* lnb = (const float*)d_in[2];
    const float* wl  = (const float*)d_in[3];
    const float* bl  = (const float*)d_in[4];
    const float* wr  = (const float*)d_in[5];
    const float* br  = (const float*)d_in[6];
    const float* wo  = (const float*)d_in[7];
    const float* bo  = (const float*)d_in[8];

    const int SMP = (256 * 72 + 2 * 64 * 36 + 512) * 4;        // 94720 B
    const int SM2 = 2 * 17408 * 2;                             // 69632 B
    const int SM3 = 2 * 18432 * 2;                             // 73728 B

    cudaFuncSetAttribute(k_proj,  cudaFuncAttributeMaxDynamicSharedMemorySize, SMP);
    cudaFuncSetAttribute(k_outer, cudaFuncAttributeMaxDynamicSharedMemorySize, SM2);
    cudaFuncSetAttribute(k_proj2, cudaFuncAttributeMaxDynamicSharedMemorySize, SM3);

    k_stats<<<4096, 256>>>(x);
    k_woT<<<128, 256>>>(wo);
    k_proj<<<512, 128, SMP>>>(x, lnw, lnb, wl, bl, wr, br);
    k_outer<<<dim3(64, 64), 256, SM2>>>();
    k_proj2<<<dim3(2, 256), 256, SM3>>>(bo, (float*)d_out);
}